// round 4
// baseline (speedup 1.0000x reference)
#include <cuda_runtime.h>
#include <cstdint>

#define PI_F 3.14159265358979323846f          /* rounds to 3.1415927f = f32(np.pi) */
#define ANG_THR 0.08726646259971647f          /* radians(5.0) */
#define EMAX 8192
#define NB 35                                 /* bucket width pi/35 > thr (2.9% margin) */
#define CAP 1024                              /* per-row CSR capacity (avg ~232) */

// -------------------- device scratch (static: no allocation allowed) --------
__device__ float g_ang[EMAX], g_nx[EMAX], g_ny[EMAX], g_off[EMAX], g_mx[EMAX], g_my[EMAX];
__device__ int   g_bkt[EMAX];
__device__ float g_sang[EMAX];                 // bucket-sorted angles
__device__ int   g_sorig[EMAX];                // bucket-sorted original indices
__device__ int   g_sbkt[EMAX];                 // bucket id per sorted position
__device__ int   g_boff[NB + 1];               // bucket offsets
__device__ unsigned g_rowcnt[EMAX];            // per-row CSR counters
__device__ unsigned g_rowj[EMAX * CAP];        // CSR column indices
__device__ float    g_rowd[EMAX * CAP];        // CSR distances
__device__ unsigned g_h1[65536];               // top-16-bit histogram
__device__ unsigned g_h2[3 * 65536];           // low-16-bit histograms (q1, mu, q3)
__device__ unsigned g_p16[3];                  // selected top-16 prefix per target
__device__ unsigned g_r2[3];                   // remaining rank per target
__device__ unsigned g_count;                   // n_pairs
__device__ float g_mu, g_margin;
__device__ float g_partial[EMAX];              // per-row loss partial sums

__device__ __forceinline__ bool pair_ok(float ai, float aj) {
    float df = fabsf(aj - ai);
    df = fminf(df, PI_F - df);
    return df < ANG_THR;
}
__device__ __forceinline__ float pair_dist(float nx, float ny, float off, float mx, float my) {
    return fabsf(nx * mx + ny * my - off);
}

// -------------------- K1: per-edge geometry + bucket + replay zeroing -------
__global__ void k_edges(const float* __restrict__ pos, const int* __restrict__ eidx, int E) {
    int idx = blockIdx.x * blockDim.x + threadIdx.x;
    if (idx >= E) return;
    // per-replay zeroing (8192 threads cover everything)
    g_rowcnt[idx] = 0;
#pragma unroll
    for (int k = 0; k < 8; k++)  g_h1[idx * 8 + k] = 0;
#pragma unroll
    for (int k = 0; k < 24; k++) g_h2[idx * 24 + k] = 0;

    int s = eidx[idx];
    int d = eidx[E + idx];
    float sx = pos[2 * s], sy = pos[2 * s + 1];
    float dx = pos[2 * d], dy = pos[2 * d + 1];
    float ddx = dx - sx, ddy = dy - sy;
    float len = fmaxf(sqrtf(ddx * ddx + ddy * ddy), 1e-8f);
    float ux = ddx / len, uy = ddy / len;
    float a = atan2f(uy, ux);
    a = fmodf(a, PI_F);
    if (a < 0.f) a += PI_F;
    g_ang[idx] = a;
    g_nx[idx] = -uy;
    g_ny[idx] = ux;
    g_off[idx] = sx * (-uy) + sy * ux;
    g_mx[idx] = (sx + dx) * 0.5f;
    g_my[idx] = (sy + dy) * 0.5f;
    int b = (int)(a * 11.140846016432674f);    // a * 35/pi
    b = (b < 0) ? 0 : ((b >= NB) ? NB - 1 : b);
    g_bkt[idx] = b;
}

// -------------------- K2: stable counting sort by bucket (1 block) ----------
__global__ void k_bsort(int E) {
    __shared__ unsigned s_cnt[NB * 256];
    __shared__ unsigned s_ws[256];
    int t = threadIdx.x;                        // 256 threads, 32 elems each
    for (int b = 0; b < NB; b++) s_cnt[b * 256 + t] = 0;
    __syncthreads();
    int base = t * 32;
    for (int k = 0; k < 32; k++) s_cnt[g_bkt[base + k] * 256 + t]++;
    __syncthreads();
    unsigned s = 0;
    for (int k = 0; k < 35; k++) s += s_cnt[t * 35 + k];
    s_ws[t] = s;
    __syncthreads();
    if (t == 0) {
        unsigned acc = 0;
        for (int k = 0; k < 256; k++) { unsigned v = s_ws[k]; s_ws[k] = acc; acc += v; }
    }
    __syncthreads();
    unsigned acc = s_ws[t];
    for (int k = 0; k < 35; k++) { unsigned v = s_cnt[t * 35 + k]; s_cnt[t * 35 + k] = acc; acc += v; }
    __syncthreads();
    if (t < NB) g_boff[t] = (int)s_cnt[t * 256];
    if (t == 0) g_boff[NB] = E;
    for (int k = 0; k < 32; k++) {
        int e = base + k;
        int b = g_bkt[e];
        unsigned p = s_cnt[b * 256 + t]++;
        g_sang[p] = g_ang[e];
        g_sorig[p] = e;
        g_sbkt[p] = b;
    }
}

// -------------------- K3: emit pairs -> row CSR + fused top-16 histogram ----
__global__ void k_emit(int E) {
    int gid = blockIdx.x * blockDim.x + threadIdx.x;
    int p = gid >> 5;
    int lane = gid & 31;
    if (p >= E) return;
    float ap = g_sang[p];
    int op = g_sorig[p];
    int b = g_sbkt[p];
    int end1 = g_boff[b + 1];
    int bn = (b + 1 == NB) ? 0 : (b + 1);
    int lo2 = g_boff[bn], hi2 = g_boff[bn + 1];
    unsigned lm = (1u << lane) - 1u;

    for (int pass = 0; pass < 2; pass++) {
        int qs = pass ? lo2 : (p + 1);
        int qe = pass ? hi2 : end1;
#pragma unroll 1
        for (int q0 = qs; q0 < qe; q0 += 32) {
            int q = q0 + lane;
            bool ok = (q < qe) && pair_ok(ap, g_sang[q]);
            int i = 0, j = 0;
            float dd = 0.f;
            bool i_is_op = false;
            if (ok) {
                int oq = g_sorig[q];
                i = min(op, oq); j = max(op, oq);
                dd = pair_dist(g_nx[i], g_ny[i], g_off[i], g_mx[j], g_my[j]);
                i_is_op = (i == op);
            }
            unsigned balA = __ballot_sync(0xffffffffu, ok && i_is_op);
            if (balA) {
                int leader = __ffs(balA) - 1;
                unsigned basec = 0;
                if (lane == leader) basec = atomicAdd(&g_rowcnt[op], (unsigned)__popc(balA));
                basec = __shfl_sync(0xffffffffu, basec, leader);
                if (ok && i_is_op) {
                    unsigned slot = basec + __popc(balA & lm);
                    if (slot < CAP) {
                        g_rowj[(unsigned)i * CAP + slot] = (unsigned)j;
                        g_rowd[(unsigned)i * CAP + slot] = dd;
                    }
                }
            }
            if (ok && !i_is_op) {
                unsigned slot = atomicAdd(&g_rowcnt[i], 1u);
                if (slot < CAP) {
                    g_rowj[(unsigned)i * CAP + slot] = (unsigned)j;
                    g_rowd[(unsigned)i * CAP + slot] = dd;
                }
            }
            if (ok) atomicAdd(&g_h1[__float_as_uint(dd) >> 16], 1u);
        }
    }
}

// -------------------- K4: resolve top-16 digit (1 block, 1024 thr) ----------
__global__ void k_resolve1() {
    __shared__ unsigned s_ws[32];
    __shared__ unsigned s_tot;
    int t = threadIdx.x;
    int lane = t & 31, wrp = t >> 5;
    unsigned loc = 0;
#pragma unroll 1
    for (int k = 0; k < 64; k++) loc += g_h1[t * 64 + k];
    unsigned v = loc;
    for (int o = 1; o < 32; o <<= 1) { unsigned u = __shfl_up_sync(0xffffffffu, v, o); if (lane >= o) v += u; }
    if (lane == 31) s_ws[wrp] = v;
    __syncthreads();
    if (t < 32) {
        unsigned w = s_ws[t];
        for (int o = 1; o < 32; o <<= 1) { unsigned u = __shfl_up_sync(0xffffffffu, w, o); if (t >= o) w += u; }
        s_ws[t] = w;
    }
    __syncthreads();
    unsigned excl = v - loc + (wrp ? s_ws[wrp - 1] : 0u);
    if (t == 1023) s_tot = excl + loc;
    __syncthreads();
    unsigned n = s_tot;
    if (t == 0) {
        g_count = n;
        g_p16[0] = 0; g_p16[1] = 0; g_p16[2] = 0;
        g_r2[0] = 0;  g_r2[1] = 0;  g_r2[2] = 0;
    }
    if (n == 0) return;
    unsigned r[3];
    { unsigned q = n / 4u; r[0] = q ? q - 1u : 0u; r[1] = n / 2u;
      unsigned a = (3u * n) / 4u; r[2] = (a < n - 1u) ? a : (n - 1u); }
    __syncthreads();
    unsigned cum = excl;
#pragma unroll 1
    for (int k = 0; k < 64; k++) {
        unsigned c = g_h1[t * 64 + k];
        if (c) {
#pragma unroll
            for (int t3 = 0; t3 < 3; t3++)
                if (r[t3] >= cum && r[t3] < cum + c) {
                    g_p16[t3] = (unsigned)(t * 64 + k);
                    g_r2[t3]  = r[t3] - cum;
                }
        }
        cum += c;
    }
}

// -------------------- K5: low-16 histograms for the 3 prefixes --------------
__global__ void k_hist2(int E) {
    int t = threadIdx.x;
    int r0 = blockIdx.x * 8;                    // 8 rows per block
    unsigned p0 = g_p16[0], p1 = g_p16[1], p2 = g_p16[2];
    for (int rr = 0; rr < 8; rr++) {
        int r = r0 + rr;
        unsigned cnt = min(g_rowcnt[r], (unsigned)CAP);
        for (unsigned e = t; e < cnt; e += 256) {
            unsigned u = __float_as_uint(g_rowd[(unsigned)r * CAP + e]);
            unsigned hi = u >> 16, lo = u & 0xffffu;
            if (hi == p0) atomicAdd(&g_h2[lo], 1u);
            if (hi == p1) atomicAdd(&g_h2[65536 + lo], 1u);
            if (hi == p2) atomicAdd(&g_h2[131072 + lo], 1u);
        }
    }
}

// -------------------- K6: resolve low-16 -> mu, margin -----------------------
__global__ void k_resolve2() {
    __shared__ unsigned s_ws[32];
    __shared__ unsigned s_low[3];
    int t = threadIdx.x;
    int lane = t & 31, wrp = t >> 5;
    if (t < 3) s_low[t] = 0;
    __syncthreads();
    for (int t3 = 0; t3 < 3; t3++) {
        unsigned base = (unsigned)t3 * 65536u;
        unsigned rank = g_r2[t3];
        unsigned loc = 0;
#pragma unroll 1
        for (int k = 0; k < 64; k++) loc += g_h2[base + t * 64 + k];
        unsigned v = loc;
        for (int o = 1; o < 32; o <<= 1) { unsigned u = __shfl_up_sync(0xffffffffu, v, o); if (lane >= o) v += u; }
        if (lane == 31) s_ws[wrp] = v;
        __syncthreads();
        if (t < 32) {
            unsigned w = s_ws[t];
            for (int o = 1; o < 32; o <<= 1) { unsigned u = __shfl_up_sync(0xffffffffu, w, o); if (t >= o) w += u; }
            s_ws[t] = w;
        }
        __syncthreads();
        unsigned cum = v - loc + (wrp ? s_ws[wrp - 1] : 0u);
#pragma unroll 1
        for (int k = 0; k < 64; k++) {
            unsigned c = g_h2[base + t * 64 + k];
            if (c && rank >= cum && rank < cum + c) s_low[t3] = (unsigned)(t * 64 + k);
            cum += c;
        }
        __syncthreads();
    }
    if (t == 0) {
        if (g_count == 0) { g_mu = 0.f; g_margin = 0.f; }
        else {
            float q1 = __uint_as_float((g_p16[0] << 16) | s_low[0]);
            float mu = __uint_as_float((g_p16[1] << 16) | s_low[1]);
            float q3 = __uint_as_float((g_p16[2] << 16) | s_low[2]);
            g_mu = mu;
            g_margin = fmaxf(q3 - q1, 1e-6f) * 0.75f;   // iqr * 0.5 * 1.5
        }
    }
}

// -------------------- K7: fused fill — build row in shared, stream out ------
// d_out layout: [0]=loss, [1,1+EE)=mask, [1+EE,1+2EE)=per_pair_loss, [1+2EE]=weight.
// Row base offsets are 1 (mod 4) floats. We shift the shared row by +1 float so
// BOTH the shared float4 reads and the global float4 stores are 16B-aligned at
// column groups starting at j=3.
__global__ void __launch_bounds__(256, 4) k_fill(float* __restrict__ dout, int E) {
    __shared__ float s_buf[EMAX + 4];           // s_row = s_buf + 1
    __shared__ float s_red[256];
    int i = blockIdx.x;
    int tid = threadIdx.x;
    float* s_row = s_buf + 1;

    // zero entire padded buffer with aligned float4 stores (2049 groups)
    float4* s4 = (float4*)s_buf;
#pragma unroll 1
    for (int k = tid; k < 2049; k += 256) s4[k] = make_float4(0.f, 0.f, 0.f, 0.f);
    __syncthreads();

    unsigned cnt = min(g_rowcnt[i], (unsigned)CAP);
    float mu = g_mu, mg = g_margin;
    for (unsigned e = tid; e < cnt; e += 256) {
        unsigned j = g_rowj[(unsigned)i * CAP + e];
        float d = g_rowd[(unsigned)i * CAP + e];
        s_row[j] = fmaxf(fabsf(d - mu) - mg, 0.f);
    }
    __syncthreads();

    // deterministic loss sum: fixed column order per thread + fixed tree
    float ls = 0.f;
#pragma unroll 1
    for (int k = 0; k < 32; k++) ls += s_row[tid * 32 + k];
    s_red[tid] = ls;
    __syncthreads();
    for (int o = 128; o > 0; o >>= 1) {
        if (tid < o) s_red[tid] += s_red[tid + o];
        __syncthreads();
    }
    if (tid == 0) g_partial[i] = s_red[0];

    size_t EE = (size_t)E * (size_t)E;
    float* omask = dout + 1 + (size_t)i * E;
    float* oloss = omask + EE;

    // 2047 aligned float4 groups: columns [3 + 4g .. 3 + 4g + 3]
#pragma unroll 1
    for (int g = tid; g < 2047; g += 256) {
        int j0 = 3 + 4 * g;
        float4 l = *(float4*)&s_row[j0];        // s_buf + 4 + 4g: aligned
        float4 m = make_float4(l.x > 0.f ? 1.f : 0.f, l.y > 0.f ? 1.f : 0.f,
                               l.z > 0.f ? 1.f : 0.f, l.w > 0.f ? 1.f : 0.f);
        __stcs((float4*)(omask + j0), m);
        __stcs((float4*)(oloss + j0), l);
    }
    if (tid < 4) {
        int j = (tid < 3) ? tid : (E - 1);
        float l = s_row[j];
        __stcs(omask + j, l > 0.f ? 1.f : 0.f);
        __stcs(oloss + j, l);
    }
}

// -------------------- K8: final deterministic reduction + scalars -----------
__global__ void k_reduce(float* __restrict__ dout, const float* __restrict__ weight,
                         long long out_size, int E) {
    __shared__ float s[1024];
    int tid = threadIdx.x;
    float v = 0.f;
#pragma unroll 1
    for (int t = tid; t < E; t += 1024) v += g_partial[t];
    s[tid] = v;
    __syncthreads();
    for (int o = 512; o > 0; o >>= 1) {
        if (tid < o) s[tid] += s[tid + o];
        __syncthreads();
    }
    if (tid == 0) {
        unsigned n = g_count;
        float denom = (n >= 1u) ? (float)n : 1.0f;
        dout[0] = s[0] / denom;
        dout[out_size - 1] = weight[0];
    }
}

// ============================================================================
extern "C" void kernel_launch(void* const* d_in, const int* in_sizes, int n_in,
                              void* d_out, int out_size) {
    const float* pos    = (const float*)d_in[0];
    // d_in[1] = adjacency: unused by the reference computation
    const int*   eidx   = (const int*)d_in[2];
    const float* weight = (const float*)d_in[3];
    int E = in_sizes[2] / 2;                    // 8192
    float* out = (float*)d_out;

    k_edges<<<(E + 255) / 256, 256>>>(pos, eidx, E);
    k_bsort<<<1, 256>>>(E);
    k_emit<<<(E * 32 + 255) / 256, 256>>>(E);
    k_resolve1<<<1, 1024>>>();
    k_hist2<<<E / 8, 256>>>(E);
    k_resolve2<<<1, 1024>>>();
    k_fill<<<E, 256>>>(out, E);
    k_reduce<<<1, 1024>>>(out, weight, (long long)out_size, E);
}

// round 5
// speedup vs baseline: 2.4633x; 2.4633x over previous
#include <cuda_runtime.h>
#include <cstdint>

#define PI_F 3.14159265358979323846f          /* rounds to 3.1415927f = f32(np.pi) */
#define ANG_THR 0.08726646259971647f          /* radians(5.0) */
#define EMAX 8192
#define NB 35                                 /* bucket width pi/35 > thr (2.9% margin) */
#define CAP 1024                              /* per-row CSR capacity (avg ~232) */

// -------------------- device scratch (static: no allocation allowed) --------
__device__ float g_ang[EMAX], g_nx[EMAX], g_ny[EMAX], g_off[EMAX], g_mx[EMAX], g_my[EMAX];
__device__ int   g_bkt[EMAX];
__device__ float g_sang[EMAX];                 // bucket-sorted angles
__device__ int   g_sorig[EMAX];                // bucket-sorted original indices
__device__ int   g_sbkt[EMAX];                 // bucket id per sorted position
__device__ int   g_boff[NB + 1];               // bucket offsets
__device__ unsigned g_rowcnt[EMAX];            // per-row CSR counters
__device__ unsigned g_rowj[EMAX * CAP];        // CSR column indices
__device__ float    g_rowd[EMAX * CAP];        // CSR distances
__device__ unsigned g_hA[4096];                // top-12-bit histogram
__device__ unsigned g_hB[3 * 4096];            // mid-12-bit histograms (q1, mu, q3)
__device__ unsigned g_hC[3 * 256];             // low-8-bit histograms
__device__ unsigned g_pre12[3], g_rk1[3];      // resolved prefixes / remaining ranks
__device__ unsigned g_pre24[3], g_rk2[3];
__device__ unsigned g_count;                   // n_pairs
__device__ float g_mu, g_margin;
__device__ unsigned long long g_lsum;          // fixed-point (2^32) loss accumulator
__device__ unsigned g_done;                    // fill-block arrival counter

__device__ __forceinline__ bool pair_ok(float ai, float aj) {
    float df = fabsf(aj - ai);
    df = fminf(df, PI_F - df);
    return df < ANG_THR;
}
__device__ __forceinline__ float pair_dist(float nx, float ny, float off, float mx, float my) {
    return fabsf(nx * mx + ny * my - off);
}

// -------------------- K1: per-edge geometry + bucket + replay zeroing -------
__global__ void k_edges(const float* __restrict__ pos, const int* __restrict__ eidx, int E) {
    int idx = blockIdx.x * blockDim.x + threadIdx.x;
    if (idx >= E) return;
    // per-replay zeroing (8192 threads cover everything)
    g_rowcnt[idx] = 0;
    if (idx < 4096) g_hA[idx] = 0;
    for (int k = idx; k < 3 * 4096; k += EMAX) g_hB[k] = 0;
    if (idx < 3 * 256) g_hC[idx] = 0;
    if (idx == 0) { g_lsum = 0ull; g_done = 0u; }

    int s = eidx[idx];
    int d = eidx[E + idx];
    float sx = pos[2 * s], sy = pos[2 * s + 1];
    float dx = pos[2 * d], dy = pos[2 * d + 1];
    float ddx = dx - sx, ddy = dy - sy;
    float len = fmaxf(sqrtf(ddx * ddx + ddy * ddy), 1e-8f);
    float ux = ddx / len, uy = ddy / len;
    float a = atan2f(uy, ux);
    a = fmodf(a, PI_F);
    if (a < 0.f) a += PI_F;
    g_ang[idx] = a;
    g_nx[idx] = -uy;
    g_ny[idx] = ux;
    g_off[idx] = sx * (-uy) + sy * ux;
    g_mx[idx] = (sx + dx) * 0.5f;
    g_my[idx] = (sy + dy) * 0.5f;
    int b = (int)(a * 11.140846016432674f);    // a * 35/pi
    b = (b < 0) ? 0 : ((b >= NB) ? NB - 1 : b);
    g_bkt[idx] = b;
}

// -------------------- K2: stable counting sort by bucket (1 block) ----------
__global__ void k_bsort(int E) {
    __shared__ unsigned s_cnt[NB * 256];
    __shared__ unsigned s_ws[256];
    int t = threadIdx.x;                        // 256 threads, 32 elems each
    for (int b = 0; b < NB; b++) s_cnt[b * 256 + t] = 0;
    __syncthreads();
    int base = t * 32;
    for (int k = 0; k < 32; k++) s_cnt[g_bkt[base + k] * 256 + t]++;
    __syncthreads();
    unsigned s = 0;
    for (int k = 0; k < 35; k++) s += s_cnt[t * 35 + k];
    s_ws[t] = s;
    __syncthreads();
    if (t == 0) {
        unsigned acc = 0;
        for (int k = 0; k < 256; k++) { unsigned v = s_ws[k]; s_ws[k] = acc; acc += v; }
    }
    __syncthreads();
    unsigned acc = s_ws[t];
    for (int k = 0; k < 35; k++) { unsigned v = s_cnt[t * 35 + k]; s_cnt[t * 35 + k] = acc; acc += v; }
    __syncthreads();
    if (t < NB) g_boff[t] = (int)s_cnt[t * 256];
    if (t == 0) g_boff[NB] = E;
    for (int k = 0; k < 32; k++) {
        int e = base + k;
        int b = g_bkt[e];
        unsigned p = s_cnt[b * 256 + t]++;
        g_sang[p] = g_ang[e];
        g_sorig[p] = e;
        g_sbkt[p] = b;
    }
}

// -------------------- K3: emit pairs -> row CSR + fused top-12 histogram ----
// grid exactly E/8 blocks of 256 (one warp per sorted position). No early returns.
__global__ void k_emit(int E) {
    __shared__ unsigned s_hA[4096];
    int tid = threadIdx.x;
    for (int k = tid; k < 4096; k += 256) s_hA[k] = 0;
    __syncthreads();

    int gid = blockIdx.x * blockDim.x + tid;
    int p = gid >> 5;
    int lane = gid & 31;
    unsigned lm = (1u << lane) - 1u;

    if (p < E) {
        float ap = g_sang[p];
        int op = g_sorig[p];
        int b = g_sbkt[p];
        int end1 = g_boff[b + 1];
        int bn = (b + 1 == NB) ? 0 : (b + 1);
        int lo2 = g_boff[bn], hi2 = g_boff[bn + 1];

        for (int pass = 0; pass < 2; pass++) {
            int qs = pass ? lo2 : (p + 1);
            int qe = pass ? hi2 : end1;
#pragma unroll 1
            for (int q0 = qs; q0 < qe; q0 += 32) {
                int q = q0 + lane;
                bool ok = (q < qe) && pair_ok(ap, g_sang[q]);
                int i = 0, j = 0;
                float dd = 0.f;
                bool i_is_op = false;
                if (ok) {
                    int oq = g_sorig[q];
                    i = min(op, oq); j = max(op, oq);
                    dd = pair_dist(g_nx[i], g_ny[i], g_off[i], g_mx[j], g_my[j]);
                    i_is_op = (i == op);
                }
                unsigned balA = __ballot_sync(0xffffffffu, ok && i_is_op);
                if (balA) {
                    int leader = __ffs(balA) - 1;
                    unsigned basec = 0;
                    if (lane == leader) basec = atomicAdd(&g_rowcnt[op], (unsigned)__popc(balA));
                    basec = __shfl_sync(0xffffffffu, basec, leader);
                    if (ok && i_is_op) {
                        unsigned slot = basec + __popc(balA & lm);
                        if (slot < CAP) {
                            g_rowj[(unsigned)i * CAP + slot] = (unsigned)j;
                            g_rowd[(unsigned)i * CAP + slot] = dd;
                        }
                    }
                }
                if (ok && !i_is_op) {
                    unsigned slot = atomicAdd(&g_rowcnt[i], 1u);
                    if (slot < CAP) {
                        g_rowj[(unsigned)i * CAP + slot] = (unsigned)j;
                        g_rowd[(unsigned)i * CAP + slot] = dd;
                    }
                }
                if (ok) atomicAdd(&s_hA[__float_as_uint(dd) >> 20], 1u);
            }
        }
    }
    __syncthreads();
    for (int k = tid; k < 4096; k += 256) {
        unsigned v = s_hA[k];
        if (v) atomicAdd(&g_hA[k], v);
    }
}

// -------------------- K4: resolve top-12 digit (1 block, 1024 thr) ----------
__global__ void k_resolveA() {
    __shared__ unsigned s_ws[32];
    __shared__ unsigned s_n;
    int t = threadIdx.x;
    int lane = t & 31, wrp = t >> 5;
    unsigned bin[4]; unsigned loc = 0;
#pragma unroll
    for (int k = 0; k < 4; k++) { bin[k] = g_hA[t * 4 + k]; loc += bin[k]; }
    unsigned v = loc;
    for (int o = 1; o < 32; o <<= 1) { unsigned u = __shfl_up_sync(0xffffffffu, v, o); if (lane >= o) v += u; }
    if (lane == 31) s_ws[wrp] = v;
    __syncthreads();
    if (t < 32) {
        unsigned w = s_ws[t];
        for (int o = 1; o < 32; o <<= 1) { unsigned u = __shfl_up_sync(0xffffffffu, w, o); if (t >= o) w += u; }
        s_ws[t] = w;
    }
    __syncthreads();
    unsigned excl = v - loc + (wrp ? s_ws[wrp - 1] : 0u);
    if (t == 1023) s_n = excl + loc;
    __syncthreads();
    unsigned n = s_n;
    if (t == 0) g_count = n;
    if (t < 3) { g_pre12[t] = 0; g_rk1[t] = 0; }
    if (n == 0) return;
    unsigned r[3];
    { unsigned q = n / 4u; r[0] = q ? q - 1u : 0u; r[1] = n / 2u;
      unsigned a = (3u * n) / 4u; r[2] = (a < n - 1u) ? a : (n - 1u); }
    __syncthreads();
    unsigned cum = excl;
#pragma unroll
    for (int k = 0; k < 4; k++) {
        unsigned c = bin[k];
        if (c) {
#pragma unroll
            for (int t3 = 0; t3 < 3; t3++)
                if (r[t3] >= cum && r[t3] < cum + c) {
                    g_pre12[t3] = (unsigned)(t * 4 + k);
                    g_rk1[t3]   = r[t3] - cum;
                }
        }
        cum += c;
    }
}

// -------------------- K5: mid-12-bit histograms (scan CSR) ------------------
__global__ void k_histB(int E) {
    int t = threadIdx.x;
    int r0 = blockIdx.x * 8;
    unsigned p0 = g_pre12[0], p1 = g_pre12[1], p2 = g_pre12[2];
    for (int rr = 0; rr < 8; rr++) {
        int r = r0 + rr;
        unsigned cnt = min(g_rowcnt[r], (unsigned)CAP);
        for (unsigned e = t; e < cnt; e += 256) {
            unsigned u = __float_as_uint(g_rowd[(unsigned)r * CAP + e]);
            unsigned hi = u >> 20, mid = (u >> 8) & 0xFFFu;
            if (hi == p0) atomicAdd(&g_hB[mid], 1u);
            if (hi == p1) atomicAdd(&g_hB[4096 + mid], 1u);
            if (hi == p2) atomicAdd(&g_hB[8192 + mid], 1u);
        }
    }
}

// -------------------- K6: resolve mid-12 (1 block, 1024 thr) ----------------
__global__ void k_resolveB() {
    __shared__ unsigned s_ws[32];
    int t = threadIdx.x;
    int lane = t & 31, wrp = t >> 5;
    for (int t3 = 0; t3 < 3; t3++) {
        unsigned base = (unsigned)t3 * 4096u;
        unsigned rank = g_rk1[t3];
        unsigned bin[4]; unsigned loc = 0;
#pragma unroll
        for (int k = 0; k < 4; k++) { bin[k] = g_hB[base + t * 4 + k]; loc += bin[k]; }
        unsigned v = loc;
        for (int o = 1; o < 32; o <<= 1) { unsigned u = __shfl_up_sync(0xffffffffu, v, o); if (lane >= o) v += u; }
        if (lane == 31) s_ws[wrp] = v;
        __syncthreads();
        if (t < 32) {
            unsigned w = s_ws[t];
            for (int o = 1; o < 32; o <<= 1) { unsigned u = __shfl_up_sync(0xffffffffu, w, o); if (t >= o) w += u; }
            s_ws[t] = w;
        }
        __syncthreads();
        unsigned cum = v - loc + (wrp ? s_ws[wrp - 1] : 0u);
#pragma unroll
        for (int k = 0; k < 4; k++) {
            unsigned c = bin[k];
            if (c && rank >= cum && rank < cum + c) {
                g_pre24[t3] = (g_pre12[t3] << 12) | (unsigned)(t * 4 + k);
                g_rk2[t3]   = rank - cum;
            }
            cum += c;
        }
        __syncthreads();
    }
}

// -------------------- K7: low-8-bit histograms (scan CSR) -------------------
__global__ void k_histC(int E) {
    int t = threadIdx.x;
    int r0 = blockIdx.x * 8;
    unsigned p0 = g_pre24[0], p1 = g_pre24[1], p2 = g_pre24[2];
    for (int rr = 0; rr < 8; rr++) {
        int r = r0 + rr;
        unsigned cnt = min(g_rowcnt[r], (unsigned)CAP);
        for (unsigned e = t; e < cnt; e += 256) {
            unsigned u = __float_as_uint(g_rowd[(unsigned)r * CAP + e]);
            unsigned hi = u >> 8, lo = u & 0xFFu;
            if (hi == p0) atomicAdd(&g_hC[lo], 1u);
            if (hi == p1) atomicAdd(&g_hC[256 + lo], 1u);
            if (hi == p2) atomicAdd(&g_hC[512 + lo], 1u);
        }
    }
}

// -------------------- K8: resolve low-8 -> mu, margin ------------------------
__global__ void k_resolveC() {
    __shared__ unsigned s_h[768];
    __shared__ unsigned s_res[3];
    int t = threadIdx.x;                        // 256 threads
    for (int k = t; k < 768; k += 256) s_h[k] = g_hC[k];
    __syncthreads();
    if (t < 3) {
        unsigned rank = g_rk2[t];
        unsigned cum = 0, sel = 255u;
        for (int b = 0; b < 256; b++) {
            unsigned c = s_h[t * 256 + b];
            if (cum + c > rank) { sel = (unsigned)b; break; }
            cum += c;
        }
        s_res[t] = (g_pre24[t] << 8) | sel;
    }
    __syncthreads();
    if (t == 0) {
        if (g_count == 0) { g_mu = 0.f; g_margin = 0.f; }
        else {
            float q1 = __uint_as_float(s_res[0]);
            float mu = __uint_as_float(s_res[1]);
            float q3 = __uint_as_float(s_res[2]);
            g_mu = mu;
            g_margin = fmaxf(q3 - q1, 1e-6f) * 0.75f;   // iqr * 0.5 * 1.5
        }
    }
}

// -------------------- K9: fused fill + deterministic loss + finalize --------
// d_out layout: [0]=loss, [1,1+EE)=mask, [1+EE,1+2EE)=per_pair_loss, [1+2EE]=weight.
// Shared row shifted by +1 float so shared float4 reads and global float4
// stores are both 16B-aligned at column groups starting at j=3.
__global__ void __launch_bounds__(256, 4) k_fill(float* __restrict__ dout, int E,
                                                 const float* __restrict__ weight,
                                                 long long out_size) {
    __shared__ float s_buf[EMAX + 4];           // s_row = s_buf + 1
    __shared__ float s_wsum[8];
    int i = blockIdx.x;
    int tid = threadIdx.x;
    float* s_row = s_buf + 1;

    float4* s4 = (float4*)s_buf;
#pragma unroll 1
    for (int k = tid; k < 2049; k += 256) s4[k] = make_float4(0.f, 0.f, 0.f, 0.f);
    __syncthreads();

    unsigned cnt = min(g_rowcnt[i], (unsigned)CAP);
    float mu = g_mu, mg = g_margin;
    for (unsigned e = tid; e < cnt; e += 256) {
        unsigned j = g_rowj[(unsigned)i * CAP + e];
        float d = g_rowd[(unsigned)i * CAP + e];
        s_row[j] = fmaxf(fabsf(d - mu) - mg, 0.f);
    }
    __syncthreads();

    // deterministic loss sum: fixed column order, fixed shfl tree, serial 8-way
    float ls = 0.f;
#pragma unroll 1
    for (int k = 0; k < 32; k++) ls += s_row[tid * 32 + k];
    for (int o = 16; o; o >>= 1) ls += __shfl_down_sync(0xffffffffu, ls, o);
    if ((tid & 31) == 0) s_wsum[tid >> 5] = ls;
    __syncthreads();

    size_t EE = (size_t)E * (size_t)E;
    float* omask = dout + 1 + (size_t)i * E;
    float* oloss = omask + EE;

#pragma unroll 1
    for (int g = tid; g < 2047; g += 256) {
        int j0 = 3 + 4 * g;
        float4 l = *(float4*)&s_row[j0];        // s_buf + 4 + 4g: aligned
        float4 m = make_float4(l.x > 0.f ? 1.f : 0.f, l.y > 0.f ? 1.f : 0.f,
                               l.z > 0.f ? 1.f : 0.f, l.w > 0.f ? 1.f : 0.f);
        __stcs((float4*)(omask + j0), m);
        __stcs((float4*)(oloss + j0), l);
    }
    if (tid < 4) {
        int j = (tid < 3) ? tid : (E - 1);
        float l = s_row[j];
        __stcs(omask + j, l > 0.f ? 1.f : 0.f);
        __stcs(oloss + j, l);
    }

    if (tid == 0) {
        double bsum = 0.0;
#pragma unroll
        for (int k = 0; k < 8; k++) bsum += (double)s_wsum[k];
        unsigned long long q = (unsigned long long)__double2ll_rn(bsum * 4294967296.0);
        atomicAdd(&g_lsum, q);
        __threadfence();
        unsigned old = atomicAdd(&g_done, 1u);
        if (old == gridDim.x - 1u) {            // last block finalizes
            unsigned long long tot = atomicAdd(&g_lsum, 0ull);
            unsigned n = g_count;
            double denom = (n >= 1u) ? (double)n : 1.0;
            dout[0] = (float)(((double)tot / 4294967296.0) / denom);
            dout[out_size - 1] = weight[0];
        }
    }
}

// ============================================================================
extern "C" void kernel_launch(void* const* d_in, const int* in_sizes, int n_in,
                              void* d_out, int out_size) {
    const float* pos    = (const float*)d_in[0];
    // d_in[1] = adjacency: unused by the reference computation
    const int*   eidx   = (const int*)d_in[2];
    const float* weight = (const float*)d_in[3];
    int E = in_sizes[2] / 2;                    // 8192
    float* out = (float*)d_out;

    k_edges<<<(E + 255) / 256, 256>>>(pos, eidx, E);
    k_bsort<<<1, 256>>>(E);
    k_emit<<<(E * 32 + 255) / 256, 256>>>(E);
    k_resolveA<<<1, 1024>>>();
    k_histB<<<E / 8, 256>>>(E);
    k_resolveB<<<1, 1024>>>();
    k_histC<<<E / 8, 256>>>(E);
    k_resolveC<<<1, 256>>>();
    k_fill<<<E, 256>>>(out, E, weight, (long long)out_size);
}

// round 6
// speedup vs baseline: 5.4898x; 2.2287x over previous
#include <cuda_runtime.h>
#include <cstdint>

#define PI_F 3.14159265358979323846f          /* rounds to 3.1415927f = f32(np.pi) */
#define ANG_THR 0.08726646259971647f          /* radians(5.0) */
#define EMAX 8192
#define NB 35                                 /* bucket width pi/35 > thr (2.9% margin) */
#define CAP 1024                              /* per-row CSR capacity (avg ~232) */

// -------------------- device scratch (static: no allocation allowed) --------
__device__ float g_ang[EMAX], g_nx[EMAX], g_ny[EMAX], g_off[EMAX], g_mx[EMAX], g_my[EMAX];
__device__ int   g_bkt[EMAX];
__device__ float g_sang[EMAX];                 // bucket-sorted angles
__device__ int   g_sorig[EMAX];                // bucket-sorted original indices
__device__ int   g_sbkt[EMAX];                 // bucket id per sorted position
__device__ int   g_boff[NB + 1];               // bucket offsets
__device__ unsigned g_rowcnt[EMAX];            // per-row CSR counters
__device__ unsigned g_rowj[EMAX * CAP];        // CSR column indices
__device__ float    g_rowd[EMAX * CAP];        // CSR distances
__device__ unsigned g_hA[4096];                // top-12-bit histogram
__device__ unsigned g_hB[3 * 4096];            // mid-12-bit histograms (q1, mu, q3)
__device__ unsigned g_hC[3 * 256];             // low-8-bit histograms
__device__ unsigned g_pre12[3], g_rk1[3];      // resolved prefixes / remaining ranks
__device__ unsigned g_pre24[3], g_rk2[3];
__device__ unsigned g_count;                   // n_pairs
__device__ float g_mu, g_margin;
__device__ unsigned long long g_lsum;          // fixed-point (2^32) loss accumulator
__device__ unsigned g_done;                    // fill-block arrival counter

__device__ __forceinline__ bool pair_ok(float ai, float aj) {
    float df = fabsf(aj - ai);
    df = fminf(df, PI_F - df);
    return df < ANG_THR;
}
__device__ __forceinline__ float pair_dist(float nx, float ny, float off, float mx, float my) {
    return fabsf(nx * mx + ny * my - off);
}

// -------------------- K1: per-edge geometry + bucket + replay zeroing -------
__global__ void k_edges(const float* __restrict__ pos, const int* __restrict__ eidx, int E) {
    int idx = blockIdx.x * blockDim.x + threadIdx.x;
    if (idx >= E) return;
    // per-replay zeroing (8192 threads cover everything)
    g_rowcnt[idx] = 0;
    if (idx < 4096) g_hA[idx] = 0;
    for (int k = idx; k < 3 * 4096; k += EMAX) g_hB[k] = 0;
    if (idx < 3 * 256) g_hC[idx] = 0;
    if (idx == 0) { g_lsum = 0ull; g_done = 0u; }

    int s = eidx[idx];
    int d = eidx[E + idx];
    float sx = pos[2 * s], sy = pos[2 * s + 1];
    float dx = pos[2 * d], dy = pos[2 * d + 1];
    float ddx = dx - sx, ddy = dy - sy;
    float len = fmaxf(sqrtf(ddx * ddx + ddy * ddy), 1e-8f);
    float ux = ddx / len, uy = ddy / len;
    float a = atan2f(uy, ux);
    a = fmodf(a, PI_F);
    if (a < 0.f) a += PI_F;
    g_ang[idx] = a;
    g_nx[idx] = -uy;
    g_ny[idx] = ux;
    g_off[idx] = sx * (-uy) + sy * ux;
    g_mx[idx] = (sx + dx) * 0.5f;
    g_my[idx] = (sy + dy) * 0.5f;
    int b = (int)(a * 11.140846016432674f);    // a * 35/pi
    b = (b < 0) ? 0 : ((b >= NB) ? NB - 1 : b);
    g_bkt[idx] = b;
}

// -------------------- K2: stable counting sort by bucket (1 block) ----------
__global__ void k_bsort(int E) {
    __shared__ unsigned s_cnt[NB * 256];
    __shared__ unsigned s_ws[256];
    int t = threadIdx.x;                        // 256 threads, 32 elems each
    for (int b = 0; b < NB; b++) s_cnt[b * 256 + t] = 0;
    __syncthreads();
    int base = t * 32;
    for (int k = 0; k < 32; k++) s_cnt[g_bkt[base + k] * 256 + t]++;
    __syncthreads();
    unsigned s = 0;
    for (int k = 0; k < 35; k++) s += s_cnt[t * 35 + k];
    s_ws[t] = s;
    __syncthreads();
    if (t == 0) {
        unsigned acc = 0;
        for (int k = 0; k < 256; k++) { unsigned v = s_ws[k]; s_ws[k] = acc; acc += v; }
    }
    __syncthreads();
    unsigned acc = s_ws[t];
    for (int k = 0; k < 35; k++) { unsigned v = s_cnt[t * 35 + k]; s_cnt[t * 35 + k] = acc; acc += v; }
    __syncthreads();
    if (t < NB) g_boff[t] = (int)s_cnt[t * 256];
    if (t == 0) g_boff[NB] = E;
    for (int k = 0; k < 32; k++) {
        int e = base + k;
        int b = g_bkt[e];
        unsigned p = s_cnt[b * 256 + t]++;
        g_sang[p] = g_ang[e];
        g_sorig[p] = e;
        g_sbkt[p] = b;
    }
}

// -------------------- K3: emit pairs -> row CSR + fused top-12 histogram ----
__global__ void k_emit(int E) {
    __shared__ unsigned s_hA[4096];
    int tid = threadIdx.x;
    for (int k = tid; k < 4096; k += 256) s_hA[k] = 0;
    __syncthreads();

    int gid = blockIdx.x * blockDim.x + tid;
    int p = gid >> 5;
    int lane = gid & 31;
    unsigned lm = (1u << lane) - 1u;

    if (p < E) {
        float ap = g_sang[p];
        int op = g_sorig[p];
        int b = g_sbkt[p];
        int end1 = g_boff[b + 1];
        int bn = (b + 1 == NB) ? 0 : (b + 1);
        int lo2 = g_boff[bn], hi2 = g_boff[bn + 1];

        for (int pass = 0; pass < 2; pass++) {
            int qs = pass ? lo2 : (p + 1);
            int qe = pass ? hi2 : end1;
#pragma unroll 1
            for (int q0 = qs; q0 < qe; q0 += 32) {
                int q = q0 + lane;
                bool ok = (q < qe) && pair_ok(ap, g_sang[q]);
                int i = 0, j = 0;
                float dd = 0.f;
                bool i_is_op = false;
                if (ok) {
                    int oq = g_sorig[q];
                    i = min(op, oq); j = max(op, oq);
                    dd = pair_dist(g_nx[i], g_ny[i], g_off[i], g_mx[j], g_my[j]);
                    i_is_op = (i == op);
                }
                unsigned balA = __ballot_sync(0xffffffffu, ok && i_is_op);
                if (balA) {
                    int leader = __ffs(balA) - 1;
                    unsigned basec = 0;
                    if (lane == leader) basec = atomicAdd(&g_rowcnt[op], (unsigned)__popc(balA));
                    basec = __shfl_sync(0xffffffffu, basec, leader);
                    if (ok && i_is_op) {
                        unsigned slot = basec + __popc(balA & lm);
                        if (slot < CAP) {
                            g_rowj[(unsigned)i * CAP + slot] = (unsigned)j;
                            g_rowd[(unsigned)i * CAP + slot] = dd;
                        }
                    }
                }
                if (ok && !i_is_op) {
                    unsigned slot = atomicAdd(&g_rowcnt[i], 1u);
                    if (slot < CAP) {
                        g_rowj[(unsigned)i * CAP + slot] = (unsigned)j;
                        g_rowd[(unsigned)i * CAP + slot] = dd;
                    }
                }
                if (ok) atomicAdd(&s_hA[__float_as_uint(dd) >> 20], 1u);
            }
        }
    }
    __syncthreads();
    for (int k = tid; k < 4096; k += 256) {
        unsigned v = s_hA[k];
        if (v) atomicAdd(&g_hA[k], v);
    }
}

// -------------------- K4: resolve top-12 digit (1 block, 1024 thr) ----------
__global__ void k_resolveA() {
    __shared__ unsigned s_ws[32];
    __shared__ unsigned s_n;
    int t = threadIdx.x;
    int lane = t & 31, wrp = t >> 5;
    unsigned bin[4]; unsigned loc = 0;
#pragma unroll
    for (int k = 0; k < 4; k++) { bin[k] = g_hA[t * 4 + k]; loc += bin[k]; }
    unsigned v = loc;
    for (int o = 1; o < 32; o <<= 1) { unsigned u = __shfl_up_sync(0xffffffffu, v, o); if (lane >= o) v += u; }
    if (lane == 31) s_ws[wrp] = v;
    __syncthreads();
    if (t < 32) {
        unsigned w = s_ws[t];
        for (int o = 1; o < 32; o <<= 1) { unsigned u = __shfl_up_sync(0xffffffffu, w, o); if (t >= o) w += u; }
        s_ws[t] = w;
    }
    __syncthreads();
    unsigned excl = v - loc + (wrp ? s_ws[wrp - 1] : 0u);
    if (t == 1023) s_n = excl + loc;
    __syncthreads();
    unsigned n = s_n;
    if (t == 0) g_count = n;
    if (t < 3) { g_pre12[t] = 0; g_rk1[t] = 0; }
    if (n == 0) return;
    unsigned r[3];
    { unsigned q = n / 4u; r[0] = q ? q - 1u : 0u; r[1] = n / 2u;
      unsigned a = (3u * n) / 4u; r[2] = (a < n - 1u) ? a : (n - 1u); }
    __syncthreads();
    unsigned cum = excl;
#pragma unroll
    for (int k = 0; k < 4; k++) {
        unsigned c = bin[k];
        if (c) {
#pragma unroll
            for (int t3 = 0; t3 < 3; t3++)
                if (r[t3] >= cum && r[t3] < cum + c) {
                    g_pre12[t3] = (unsigned)(t * 4 + k);
                    g_rk1[t3]   = r[t3] - cum;
                }
        }
        cum += c;
    }
}

// -------------------- K5: mid-12-bit histograms (scan CSR) ------------------
__global__ void k_histB(int E) {
    int t = threadIdx.x;
    int r0 = blockIdx.x * 8;
    unsigned p0 = g_pre12[0], p1 = g_pre12[1], p2 = g_pre12[2];
    for (int rr = 0; rr < 8; rr++) {
        int r = r0 + rr;
        unsigned cnt = min(g_rowcnt[r], (unsigned)CAP);
        for (unsigned e = t; e < cnt; e += 256) {
            unsigned u = __float_as_uint(g_rowd[(unsigned)r * CAP + e]);
            unsigned hi = u >> 20, mid = (u >> 8) & 0xFFFu;
            if (hi == p0) atomicAdd(&g_hB[mid], 1u);
            if (hi == p1) atomicAdd(&g_hB[4096 + mid], 1u);
            if (hi == p2) atomicAdd(&g_hB[8192 + mid], 1u);
        }
    }
}

// -------------------- K6: resolve mid-12 (1 block, 1024 thr) ----------------
__global__ void k_resolveB() {
    __shared__ unsigned s_ws[32];
    int t = threadIdx.x;
    int lane = t & 31, wrp = t >> 5;
    for (int t3 = 0; t3 < 3; t3++) {
        unsigned base = (unsigned)t3 * 4096u;
        unsigned rank = g_rk1[t3];
        unsigned bin[4]; unsigned loc = 0;
#pragma unroll
        for (int k = 0; k < 4; k++) { bin[k] = g_hB[base + t * 4 + k]; loc += bin[k]; }
        unsigned v = loc;
        for (int o = 1; o < 32; o <<= 1) { unsigned u = __shfl_up_sync(0xffffffffu, v, o); if (lane >= o) v += u; }
        if (lane == 31) s_ws[wrp] = v;
        __syncthreads();
        if (t < 32) {
            unsigned w = s_ws[t];
            for (int o = 1; o < 32; o <<= 1) { unsigned u = __shfl_up_sync(0xffffffffu, w, o); if (t >= o) w += u; }
            s_ws[t] = w;
        }
        __syncthreads();
        unsigned cum = v - loc + (wrp ? s_ws[wrp - 1] : 0u);
#pragma unroll
        for (int k = 0; k < 4; k++) {
            unsigned c = bin[k];
            if (c && rank >= cum && rank < cum + c) {
                g_pre24[t3] = (g_pre12[t3] << 12) | (unsigned)(t * 4 + k);
                g_rk2[t3]   = rank - cum;
            }
            cum += c;
        }
        __syncthreads();
    }
}

// -------------------- K7: low-8-bit histograms (scan CSR) -------------------
__global__ void k_histC(int E) {
    int t = threadIdx.x;
    int r0 = blockIdx.x * 8;
    unsigned p0 = g_pre24[0], p1 = g_pre24[1], p2 = g_pre24[2];
    for (int rr = 0; rr < 8; rr++) {
        int r = r0 + rr;
        unsigned cnt = min(g_rowcnt[r], (unsigned)CAP);
        for (unsigned e = t; e < cnt; e += 256) {
            unsigned u = __float_as_uint(g_rowd[(unsigned)r * CAP + e]);
            unsigned hi = u >> 8, lo = u & 0xFFu;
            if (hi == p0) atomicAdd(&g_hC[lo], 1u);
            if (hi == p1) atomicAdd(&g_hC[256 + lo], 1u);
            if (hi == p2) atomicAdd(&g_hC[512 + lo], 1u);
        }
    }
}

// -------------------- K8: resolve low-8 -> mu, margin ------------------------
__global__ void k_resolveC() {
    __shared__ unsigned s_h[768];
    __shared__ unsigned s_res[3];
    int t = threadIdx.x;                        // 256 threads
    for (int k = t; k < 768; k += 256) s_h[k] = g_hC[k];
    __syncthreads();
    if (t < 3) {
        unsigned rank = g_rk2[t];
        unsigned cum = 0, sel = 255u;
        for (int b = 0; b < 256; b++) {
            unsigned c = s_h[t * 256 + b];
            if (cum + c > rank) { sel = (unsigned)b; break; }
            cum += c;
        }
        s_res[t] = (g_pre24[t] << 8) | sel;
    }
    __syncthreads();
    if (t == 0) {
        if (g_count == 0) { g_mu = 0.f; g_margin = 0.f; }
        else {
            float q1 = __uint_as_float(s_res[0]);
            float mu = __uint_as_float(s_res[1]);
            float q3 = __uint_as_float(s_res[2]);
            g_mu = mu;
            g_margin = fmaxf(q3 - q1, 1e-6f) * 0.75f;   // iqr * 0.5 * 1.5
        }
    }
}

// -------------------- K9: fused fill + deterministic loss + finalize --------
// d_out layout: [0]=loss, [1,1+EE)=mask, [1+EE,1+2EE)=per_pair_loss, [1+2EE]=weight.
// Shared row shifted by +1 float so shared float4 reads and global float4
// stores are both 16B-aligned at column groups starting at j=3.
// Loss is summed DIRECTLY from CSR entries during the scatter (each pair occurs
// exactly once in row i) — no shared read-back, no bank conflicts.
__global__ void __launch_bounds__(256, 4) k_fill(float* __restrict__ dout, int E,
                                                 const float* __restrict__ weight,
                                                 long long out_size) {
    __shared__ float s_buf[EMAX + 4];           // s_row = s_buf + 1
    __shared__ float s_wsum[8];
    int i = blockIdx.x;
    int tid = threadIdx.x;
    float* s_row = s_buf + 1;

    float4* s4 = (float4*)s_buf;
#pragma unroll 1
    for (int k = tid; k < 2049; k += 256) s4[k] = make_float4(0.f, 0.f, 0.f, 0.f);
    __syncthreads();

    unsigned cnt = min(g_rowcnt[i], (unsigned)CAP);
    float mu = g_mu, mg = g_margin;
    float ls = 0.f;
    for (unsigned e = tid; e < cnt; e += 256) {
        unsigned j = g_rowj[(unsigned)i * CAP + e];
        float d = g_rowd[(unsigned)i * CAP + e];
        float l = fmaxf(fabsf(d - mu) - mg, 0.f);
        s_row[j] = l;
        ls += l;                                 // fused loss accumulation
    }
    // deterministic: fixed e->thread map + fixed shfl tree + fixed 8-way serial
    for (int o = 16; o; o >>= 1) ls += __shfl_down_sync(0xffffffffu, ls, o);
    if ((tid & 31) == 0) s_wsum[tid >> 5] = ls;
    __syncthreads();

    size_t EE = (size_t)E * (size_t)E;
    float* omask = dout + 1 + (size_t)i * E;
    float* oloss = omask + EE;

#pragma unroll 1
    for (int g = tid; g < 2047; g += 256) {
        int j0 = 3 + 4 * g;
        float4 l = *(float4*)&s_row[j0];        // s_buf + 4 + 4g: aligned
        float4 m = make_float4(l.x > 0.f ? 1.f : 0.f, l.y > 0.f ? 1.f : 0.f,
                               l.z > 0.f ? 1.f : 0.f, l.w > 0.f ? 1.f : 0.f);
        __stcs((float4*)(omask + j0), m);
        __stcs((float4*)(oloss + j0), l);
    }
    if (tid < 4) {
        int j = (tid < 3) ? tid : (E - 1);
        float l = s_row[j];
        __stcs(omask + j, l > 0.f ? 1.f : 0.f);
        __stcs(oloss + j, l);
    }

    if (tid == 0) {
        double bsum = 0.0;
#pragma unroll
        for (int k = 0; k < 8; k++) bsum += (double)s_wsum[k];
        unsigned long long q = (unsigned long long)__double2ll_rn(bsum * 4294967296.0);
        atomicAdd(&g_lsum, q);
        __threadfence();
        unsigned old = atomicAdd(&g_done, 1u);
        if (old == gridDim.x - 1u) {            // last block finalizes
            unsigned long long tot = atomicAdd(&g_lsum, 0ull);
            unsigned n = g_count;
            double denom = (n >= 1u) ? (double)n : 1.0;
            dout[0] = (float)(((double)tot / 4294967296.0) / denom);
            dout[out_size - 1] = weight[0];
        }
    }
}

// ============================================================================
extern "C" void kernel_launch(void* const* d_in, const int* in_sizes, int n_in,
                              void* d_out, int out_size) {
    const float* pos    = (const float*)d_in[0];
    // d_in[1] = adjacency: unused by the reference computation
    const int*   eidx   = (const int*)d_in[2];
    const float* weight = (const float*)d_in[3];
    int E = in_sizes[2] / 2;                    // 8192
    float* out = (float*)d_out;

    k_edges<<<(E + 255) / 256, 256>>>(pos, eidx, E);
    k_bsort<<<1, 256>>>(E);
    k_emit<<<(E * 32 + 255) / 256, 256>>>(E);
    k_resolveA<<<1, 1024>>>();
    k_histB<<<E / 8, 256>>>(E);
    k_resolveB<<<1, 1024>>>();
    k_histC<<<E / 8, 256>>>(E);
    k_resolveC<<<1, 256>>>();
    k_fill<<<E, 256>>>(out, E, weight, (long long)out_size);
}